// round 12
// baseline (speedup 1.0000x reference)
#include <cuda_runtime.h>

#define NH 16
#define HD 64
#define BB 2
#define SS 2048
#define DD 1024
#define ND (NH*HD)          // 1024
#define BHSD (BB*NH*SS*HD)  // 4,194,304 elems per tensor

// scratch as TF32 bit patterns: Q,K = [bh][s][d]; V = [bh][d][s] (transposed)
__device__ unsigned g_scr[3][BHSD];

// log2(e) and scaled mask constants
#define QSC 0.18033688011112042f          /* 0.125 * log2(e) */
#define CMSK 1.4426950408889634e10f       /* 1e10 * log2(e); ulp=1024 >> |scores| */

__device__ __forceinline__ unsigned f2tf(float x) {
    unsigned r; asm("cvt.rna.tf32.f32 %0, %1;" : "=r"(r) : "f"(x)); return r;
}
__device__ __forceinline__ float ex2(float x) {
    float r; asm("ex2.approx.f32 %0, %1;" : "=f"(r) : "f"(x)); return r;
}

__device__ __forceinline__ void mma8(float* c, const unsigned* a, const unsigned* b) {
    asm volatile(
        "mma.sync.aligned.m16n8k8.row.col.f32.tf32.tf32.f32 "
        "{%0,%1,%2,%3}, {%4,%5,%6,%7}, {%8,%9}, {%0,%1,%2,%3};\n"
        : "+f"(c[0]), "+f"(c[1]), "+f"(c[2]), "+f"(c[3])
        : "r"(a[0]), "r"(a[1]), "r"(a[2]), "r"(a[3]), "r"(b[0]), "r"(b[1]));
}

__device__ __forceinline__ void split2(float x, unsigned& h, unsigned& l) {
    unsigned hb = f2tf(x);
    float r = x - __uint_as_float(hb);
    h = hb; l = f2tf(r);
}

__device__ __forceinline__ void cp16(unsigned smem_addr, const void* gptr) {
    asm volatile("cp.async.cg.shared.global [%0], [%1], 16;"
                 :: "r"(smem_addr), "l"(gptr));
}
#define CP_COMMIT() asm volatile("cp.async.commit_group;" ::: "memory")
#define CP_WAIT0()  asm volatile("cp.async.wait_group 0;" ::: "memory")

// ---------------------------------------------------------------------------
// Projections: A[4096,1024] @ W[1024,1024] -> g_scr[z] as TF32.
// 2-term split: (Ah + Al) @ tf32(W), split/cvt at fragment-load time.
// BM=128,BN=128,BK=16; 4 warps, warp tile 64x64 (2x2 warp grid).
// Raw fp32 tiles double-buffered in smem via cp.async: copy of stage i+1
// fully overlaps compute of stage i; one barrier per iteration.
// Per-C-element accumulation order unchanged => bit-identical output.
// ---------------------------------------------------------------------------
__global__ __launch_bounds__(128) void proj_kernel(
    const float* __restrict__ q, const float* __restrict__ k, const float* __restrict__ v,
    const float* __restrict__ Wq, const float* __restrict__ Wk, const float* __restrict__ Wv)
{
    __shared__ float sbuf[2 * 4672];     // per stage: A[128][20] + W[16][132]

    const int which = blockIdx.z;
    const float* A = which == 0 ? q : (which == 1 ? k : v);
    const float* W = which == 0 ? Wq : (which == 1 ? Wk : Wv);

    const int tid = threadIdx.x;
    const int lane = tid & 31;
    const int w = tid >> 5;              // 0..3
    const int gid = lane >> 2, tig = lane & 3;
    const int wm = w >> 1, wn = w & 1;   // 2x2 warp grid, warp tile 64x64
    const int m0 = blockIdx.y * 128, n0 = blockIdx.x * 128;

    const int am = tid;                  // A row 0..127 (16 k-floats per thread)
    const int wr = tid >> 4;             // W rows wr and wr+8
    const int wc = (tid & 15) * 8;       // 8 cols per row

    const float* Ap = A + (size_t)(m0 + am) * DD;
    const float* Wp = W + (size_t)wr * ND + n0 + wc;

    // smem byte addresses for this thread's cp.async targets, per stage
    unsigned sb = (unsigned)__cvta_generic_to_shared(sbuf);
    unsigned a_dst[2], w_dst0[2], w_dst1[2];
    #pragma unroll
    for (int s = 0; s < 2; s++) {
        unsigned base = sb + s * 4672 * 4;
        a_dst[s]  = base + (am * 20) * 4;
        w_dst0[s] = base + (2560 + wr * 132 + wc) * 4;
        w_dst1[s] = base + (2560 + (wr + 8) * 132 + wc) * 4;
    }

    float C[4][8][4];
    #pragma unroll
    for (int i = 0; i < 4; i++)
        #pragma unroll
        for (int j = 0; j < 8; j++)
            #pragma unroll
            for (int e = 0; e < 4; e++) C[i][j][e] = 0.f;

    // prologue: stage 0 (k0 = 0)
    {
        cp16(a_dst[0],      Ap);
        cp16(a_dst[0] + 16, Ap + 4);
        cp16(a_dst[0] + 32, Ap + 8);
        cp16(a_dst[0] + 48, Ap + 12);
        cp16(w_dst0[0],      Wp);
        cp16(w_dst0[0] + 16, Wp + 4);
        cp16(w_dst1[0],      Wp + (size_t)8 * ND);
        cp16(w_dst1[0] + 16, Wp + (size_t)8 * ND + 4);
        CP_COMMIT();
    }

    const int NIT = DD / 16;             // 64
    for (int it = 0; it < NIT; it++) {
        CP_WAIT0();
        __syncthreads();

        // issue stage it+1 (overlaps compute of stage it)
        if (it + 1 < NIT) {
            const int nk = (it + 1) * 16;
            const int s = (it + 1) & 1;
            cp16(a_dst[s],      Ap + nk);
            cp16(a_dst[s] + 16, Ap + nk + 4);
            cp16(a_dst[s] + 32, Ap + nk + 8);
            cp16(a_dst[s] + 48, Ap + nk + 12);
            cp16(w_dst0[s],      Wp + (size_t)nk * ND);
            cp16(w_dst0[s] + 16, Wp + (size_t)nk * ND + 4);
            cp16(w_dst1[s],      Wp + (size_t)(nk + 8) * ND);
            cp16(w_dst1[s] + 16, Wp + (size_t)(nk + 8) * ND + 4);
            CP_COMMIT();
        }

        const float* Ab = sbuf + (it & 1) * 4672;
        const float* Wb = Ab + 2560;

        #pragma unroll
        for (int ks = 0; ks < 2; ks++) {
            const int kk = ks * 8;
            unsigned ah[4][4], al[4][4], bh[8][2];
            #pragma unroll
            for (int mf = 0; mf < 4; mf++) {
                int r = wm * 64 + mf * 16 + gid;
                split2(Ab[r * 20 + kk + tig],           ah[mf][0], al[mf][0]);
                split2(Ab[(r + 8) * 20 + kk + tig],     ah[mf][1], al[mf][1]);
                split2(Ab[r * 20 + kk + tig + 4],       ah[mf][2], al[mf][2]);
                split2(Ab[(r + 8) * 20 + kk + tig + 4], ah[mf][3], al[mf][3]);
            }
            #pragma unroll
            for (int nf = 0; nf < 8; nf++) {
                int c = wn * 64 + nf * 8 + gid;
                bh[nf][0] = f2tf(Wb[(kk + tig) * 132 + c]);
                bh[nf][1] = f2tf(Wb[(kk + tig + 4) * 132 + c]);
            }
            #pragma unroll
            for (int mf = 0; mf < 4; mf++)
                #pragma unroll
                for (int nf = 0; nf < 8; nf++) {
                    mma8(C[mf][nf], al[mf], bh[nf]);
                    mma8(C[mf][nf], ah[mf], bh[nf]);
                }
        }
    }

    unsigned* out = g_scr[which];
    if (which < 2) {
        #pragma unroll
        for (int mf = 0; mf < 4; mf++) {
            int R = m0 + wm * 64 + mf * 16 + gid;
            #pragma unroll
            for (int half = 0; half < 2; half++) {
                int Rr = R + half * 8;
                int bb = Rr >> 11;
                int s  = Rr & 2047;
                #pragma unroll
                for (int nf = 0; nf < 8; nf++) {
                    int Cc = n0 + wn * 64 + nf * 8 + tig * 2;
                    int hh = Cc >> 6, dd = Cc & 63;
                    size_t addr = ((size_t)(bb * NH + hh) * SS + s) * HD + dd;
                    uint2 vv;
                    vv.x = f2tf(C[mf][nf][half * 2 + 0]);
                    vv.y = f2tf(C[mf][nf][half * 2 + 1]);
                    *(uint2*)&out[addr] = vv;
                }
            }
        }
    } else {
        // V: [bh][d][s] via smem staging, coalesced stores
        float (*stg)[129] = (float(*)[129])sbuf;
        #pragma unroll
        for (int ch = 0; ch < 2; ch++) {
            __syncthreads();
            if (wm == ch) {
                #pragma unroll
                for (int mf = 0; mf < 4; mf++)
                    #pragma unroll
                    for (int half = 0; half < 2; half++) {
                        int rr = mf * 16 + half * 8 + gid;
                        #pragma unroll
                        for (int nf = 0; nf < 8; nf++) {
                            int cc = wn * 64 + nf * 8 + tig * 2;
                            stg[rr][cc]     = C[mf][nf][half * 2 + 0];
                            stg[rr][cc + 1] = C[mf][nf][half * 2 + 1];
                        }
                    }
            }
            __syncthreads();
            const int base_s = m0 + ch * 64;
            const int bb = base_s >> 11;
            const int s_loc = base_s & 2047;
            #pragma unroll
            for (int cc = 0; cc < 32; cc++) {
                int c = w * 32 + cc;
                int hh = (n0 + c) >> 6, dd = (n0 + c) & 63;
                unsigned* dst = out + ((size_t)(bb * NH + hh) * HD + dd) * SS + s_loc;
                #pragma unroll
                for (int sg = 0; sg < 2; sg++) {
                    int s = sg * 32 + lane;
                    dst[s] = f2tf(stg[s][c]);
                }
            }
        }
    }
}

// ---------------------------------------------------------------------------
// Flash attention (round-10/11, unchanged). TF32 mma. 128-q tile, 4 warps x
// 32 rows (two m-frags share K/V fragment loads). 64-key tiles, 2 CTAs/SM.
// P stays in registers; K/V double-buffered; one __syncthreads per tile.
// ---------------------------------------------------------------------------
__global__ __launch_bounds__(128, 2) void attn_kernel(
    const int* __restrict__ v_mask, const int* __restrict__ q_mask,
    float* __restrict__ out)
{
    extern __shared__ unsigned smu[];
    unsigned* Qp = smu;                  // [128][68] permuted
    unsigned* KV = smu + 128 * 68;       // [2][ K:64*68 | V:64*68 ]
    float* kbb  = (float*)(KV + 4 * 64 * 68);   // [2][64]

    const int tid = threadIdx.x;
    const int lane = tid & 31;
    const int w = tid >> 5;              // 0..3
    const int gid = lane >> 2, tig = lane & 3;
    const int qt = gridDim.x - 1 - blockIdx.x;
    const int bh = blockIdx.y;
    const int b = bh >> 4, h = bh & 15;
    const int q0 = qt * 128;
    const int kt_hi = (q0 + 127) >> 6;
    const int NT = SS / 64;

    const unsigned* Qg = g_scr[0] + (size_t)bh * SS * HD;
    const unsigned* Kg = g_scr[1] + (size_t)bh * SS * HD;
    const unsigned* Vg = g_scr[2] + (size_t)bh * HD * SS;

    // load Q tile (permuted), folding in 0.125*log2e; 1 row per thread
    {
        const int lr = tid;
        #pragma unroll
        for (int j = 0; j < 16; j++) {
            int c0 = j * 4;
            uint4 vv = *(const uint4*)(Qg + (size_t)(q0 + lr) * HD + c0);
            int base = ((c0 >> 3) << 1) + ((c0 >> 2) & 1);
            Qp[lr * 68 + base]      = f2tf(__uint_as_float(vv.x) * QSC);
            Qp[lr * 68 + 16 + base] = f2tf(__uint_as_float(vv.y) * QSC);
            Qp[lr * 68 + 32 + base] = f2tf(__uint_as_float(vv.z) * QSC);
            Qp[lr * 68 + 48 + base] = f2tf(__uint_as_float(vv.w) * QSC);
        }
    }

    const float NEG_INF = __int_as_float(0xff800000);
    float m[2][2] = {{NEG_INF, NEG_INF}, {NEG_INF, NEG_INF}};
    float l[2][2] = {{0.f, 0.f}, {0.f, 0.f}};
    float acc[2][8][4];
    #pragma unroll
    for (int mf = 0; mf < 2; mf++)
        #pragma unroll
        for (int of = 0; of < 8; of++)
            #pragma unroll
            for (int e = 0; e < 4; e++) acc[mf][of][e] = 0.f;

    int deg = 0;
    const int rq = w * 32 + gid;         // m-frag0 base row; m-frag1 at +16
    const int llr = tid >> 1;            // K/V row 0..63
    const int lgh = (tid & 1) * 2;       // group base: 0 or 2
    const int koff = ((gid >> 1) + ((gid & 1) << 2)) * 68 + tig * 16;
    const int qoff0 = rq * 68 + tig * 16;
    const int qoff1 = (rq + 8) * 68 + tig * 16;
    const int qoff2 = (rq + 16) * 68 + tig * 16;
    const int qoff3 = (rq + 24) * 68 + tig * 16;

    int stsb[2][4];
    #pragma unroll
    for (int g = 0; g < 2; g++)
        #pragma unroll
        for (int j = 0; j < 4; j++) {
            int c0 = (lgh + g) * 16 + j * 4;
            stsb[g][j] = llr * 68 + ((c0 >> 3) << 1) + ((c0 >> 2) & 1);
        }

    uint4 rk[2][4], rv[2][4];
    float rkb = 0.f;

    // prologue: tile 0 -> buffer 0
    #pragma unroll
    for (int g = 0; g < 2; g++)
        #pragma unroll
        for (int j = 0; j < 4; j++) {
            int c0 = (lgh + g) * 16 + j * 4;
            rk[g][j] = *(const uint4*)(Kg + (size_t)llr * HD + c0);
            rv[g][j] = *(const uint4*)(Vg + (size_t)llr * SS + c0);
        }
    if (tid < 64) rkb = v_mask[b * SS + tid] ? 0.f : -CMSK;
    {
        unsigned* Kb = KV;
        unsigned* Vb = KV + 64 * 68;
        #pragma unroll
        for (int g = 0; g < 2; g++)
            #pragma unroll
            for (int j = 0; j < 4; j++) {
                Kb[stsb[g][j]]      = rk[g][j].x;  Kb[stsb[g][j] + 16] = rk[g][j].y;
                Kb[stsb[g][j] + 32] = rk[g][j].z;  Kb[stsb[g][j] + 48] = rk[g][j].w;
                Vb[stsb[g][j]]      = rv[g][j].x;  Vb[stsb[g][j] + 16] = rv[g][j].y;
                Vb[stsb[g][j] + 32] = rv[g][j].z;  Vb[stsb[g][j] + 48] = rv[g][j].w;
            }
        if (tid < 64) kbb[tid] = rkb;
    }
    __syncthreads();

    for (int kt = 0; kt < NT; kt++) {
        if (kt > kt_hi && !deg) break;
        const int k0 = kt * 64;
        const int cur = kt & 1, nxt = cur ^ 1;
        const unsigned* Kp = KV + cur * (2 * 64 * 68);
        const unsigned* Vp = Kp + 64 * 68;
        const float* kb = kbb + cur * 64;
        const bool pf = (kt + 1 < NT);

        // ---- QK: both m-frags share each K fragment load ----
        float sc[2][8][4];
        #pragma unroll
        for (int mf = 0; mf < 2; mf++)
            #pragma unroll
            for (int nf = 0; nf < 8; nf++)
                #pragma unroll
                for (int e = 0; e < 4; e++) sc[mf][nf][e] = 0.f;

        #pragma unroll
        for (int j = 0; j < 4; j++) {
            uint4 a0 = *(const uint4*)&Qp[qoff0 + j * 4];
            uint4 a1 = *(const uint4*)&Qp[qoff1 + j * 4];
            uint4 a2 = *(const uint4*)&Qp[qoff2 + j * 4];
            uint4 a3 = *(const uint4*)&Qp[qoff3 + j * 4];
            unsigned Ae0[4] = {a0.x, a1.x, a0.y, a1.y};
            unsigned Ao0[4] = {a0.z, a1.z, a0.w, a1.w};
            unsigned Ae1[4] = {a2.x, a3.x, a2.y, a3.y};
            unsigned Ao1[4] = {a2.z, a3.z, a2.w, a3.w};
            #pragma unroll
            for (int nf = 0; nf < 8; nf++) {
                uint4 bv = *(const uint4*)&Kp[nf * 544 + koff + j * 4];
                unsigned Be[2] = {bv.x, bv.y};
                unsigned Bo[2] = {bv.z, bv.w};
                mma8(sc[0][nf], Ae0, Be);
                mma8(sc[0][nf], Ao0, Bo);
                mma8(sc[1][nf], Ae1, Be);
                mma8(sc[1][nf], Ao1, Bo);
            }
        }

        // ---- prefetch tile kt+1 (LDG overlapped by softmax + PV) ----
        if (pf) {
            const int nk0 = k0 + 64;
            #pragma unroll
            for (int g = 0; g < 2; g++)
                #pragma unroll
                for (int j = 0; j < 4; j++) {
                    int c0 = (lgh + g) * 16 + j * 4;
                    rk[g][j] = *(const uint4*)(Kg + (size_t)(nk0 + llr) * HD + c0);
                    rv[g][j] = *(const uint4*)(Vg + (size_t)llr * SS + nk0 + c0);
                }
            if (tid < 64) rkb = v_mask[b * SS + nk0 + tid] ? 0.f : -CMSK;
        }

        // ---- mask + online softmax; sc[mf][nf][2i+jj] <-> key nf*8+tig+4*jj ----
        float kb0[8], kb1[8];
        #pragma unroll
        for (int nf = 0; nf < 8; nf++) {
            kb0[nf] = kb[nf * 8 + tig];
            kb1[nf] = kb[nf * 8 + tig + 4];
        }
        #pragma unroll
        for (int mf = 0; mf < 2; mf++)
            #pragma unroll
            for (int i = 0; i < 2; i++) {
                int qg = q0 + rq + mf * 16 + 8 * i;
                float mx = NEG_INF;
                #pragma unroll
                for (int nf = 0; nf < 8; nf++) {
                    float s0 = sc[mf][nf][2 * i + 0] + kb0[nf];
                    float s1 = sc[mf][nf][2 * i + 1] + kb1[nf];
                    if (k0 + nf * 8 + tig > qg)     s0 -= CMSK;
                    if (k0 + nf * 8 + tig + 4 > qg) s1 -= CMSK;
                    sc[mf][nf][2 * i + 0] = s0;
                    sc[mf][nf][2 * i + 1] = s1;
                    mx = fmaxf(mx, fmaxf(s0, s1));
                }
                mx = fmaxf(mx, __shfl_xor_sync(0xffffffffu, mx, 1));
                mx = fmaxf(mx, __shfl_xor_sync(0xffffffffu, mx, 2));
                float nm = fmaxf(m[mf][i], mx);
                float rs = 0.f;
                #pragma unroll
                for (int nf = 0; nf < 8; nf++)
                    #pragma unroll
                    for (int jj = 0; jj < 2; jj++) {
                        float p = ex2(sc[mf][nf][2 * i + jj] - nm);
                        rs += p;
                        sc[mf][nf][2 * i + jj] = __uint_as_float(f2tf(p));
                    }
                rs += __shfl_xor_sync(0xffffffffu, rs, 1);
                rs += __shfl_xor_sync(0xffffffffu, rs, 2);
                float alpha = ex2(m[mf][i] - nm);
                l[mf][i] = l[mf][i] * alpha + rs;
                m[mf][i] = nm;
                #pragma unroll
                for (int of = 0; of < 8; of++) {
                    acc[mf][of][2 * i + 0] *= alpha;
                    acc[mf][of][2 * i + 1] *= alpha;
                }
            }

        // ---- PV: both m-frags share each V fragment load ----
        #pragma unroll
        for (int of = 0; of < 8; of++) {
            const unsigned* vb = &Vp[(of * 8 + gid) * 68 + tig * 16];
            uint4 ww[4];
            ww[0] = *(const uint4*)(vb);
            ww[1] = *(const uint4*)(vb + 4);
            ww[2] = *(const uint4*)(vb + 8);
            ww[3] = *(const uint4*)(vb + 12);
            #pragma unroll
            for (int nf = 0; nf < 8; nf++) {
                unsigned Bf[2];
                if ((nf & 1) == 0) { Bf[0] = ((const unsigned*)&ww[nf >> 1])[0];
                                     Bf[1] = ((const unsigned*)&ww[nf >> 1])[1]; }
                else               { Bf[0] = ((const unsigned*)&ww[nf >> 1])[2];
                                     Bf[1] = ((const unsigned*)&ww[nf >> 1])[3]; }
                #pragma unroll
                for (int mf = 0; mf < 2; mf++) {
                    unsigned Af[4] = {__float_as_uint(sc[mf][nf][0]), __float_as_uint(sc[mf][nf][2]),
                                      __float_as_uint(sc[mf][nf][1]), __float_as_uint(sc[mf][nf][3])};
                    mma8(acc[mf][of], Af, Bf);
                }
            }
        }

        // ---- STS prefetched tile into the other buffer ----
        if (pf) {
            unsigned* Kb = KV + nxt * (2 * 64 * 68);
            unsigned* Vb = Kb + 64 * 68;
            #pragma unroll
            for (int g = 0; g < 2; g++)
                #pragma unroll
                for (int j = 0; j < 4; j++) {
                    Kb[stsb[g][j]]      = rk[g][j].x;  Kb[stsb[g][j] + 16] = rk[g][j].y;
                    Kb[stsb[g][j] + 32] = rk[g][j].z;  Kb[stsb[g][j] + 48] = rk[g][j].w;
                    Vb[stsb[g][j]]      = rv[g][j].x;  Vb[stsb[g][j] + 16] = rv[g][j].y;
                    Vb[stsb[g][j] + 32] = rv[g][j].z;  Vb[stsb[g][j] + 48] = rv[g][j].w;
                }
            if (tid < 64) kbb[nxt * 64 + tid] = rkb;
        }

        // ---- single barrier per tile (doubles as degenerate-row vote) ----
        if (kt == kt_hi)
            deg = __syncthreads_or((m[0][0] < -1e10f) || (m[0][1] < -1e10f) ||
                                   (m[1][0] < -1e10f) || (m[1][1] < -1e10f));
        else
            __syncthreads();
    }

    // epilogue
    #pragma unroll
    for (int mf = 0; mf < 2; mf++)
        #pragma unroll
        for (int i = 0; i < 2; i++) {
            int qg = q0 + rq + mf * 16 + 8 * i;
            float qm = (float)q_mask[b * SS + qg];
            float f = qm / l[mf][i];
            #pragma unroll
            for (int of = 0; of < 8; of++) {
                float2 o = make_float2(acc[mf][of][2 * i + 0] * f, acc[mf][of][2 * i + 1] * f);
                *(float2*)(out + ((size_t)b * SS + qg) * ND + h * HD + of * 8 + tig * 2) = o;
            }
        }
}

// ---------------------------------------------------------------------------
extern "C" void kernel_launch(void* const* d_in, const int* in_sizes, int n_in,
                              void* d_out, int out_size)
{
    const float* q  = (const float*)d_in[0];
    const float* k  = (const float*)d_in[1];
    const float* v  = (const float*)d_in[2];
    const int* vmask = (const int*)d_in[3];
    const int* qmask = (const int*)d_in[4];
    const float* Wq = (const float*)d_in[5];
    const float* Wk = (const float*)d_in[6];
    const float* Wv = (const float*)d_in[7];
    float* out = (float*)d_out;

    const int smem_attn = (128 * 68 + 4 * 64 * 68 + 2 * 64) * 4;   // 104,960 B
    cudaFuncSetAttribute(attn_kernel, cudaFuncAttributeMaxDynamicSharedMemorySize, smem_attn);

    dim3 gp(ND / 128, (BB * SS) / 128, 3);   // (8, 32, 3)
    proj_kernel<<<gp, 128>>>(q, k, v, Wq, Wk, Wv);

    dim3 ga(SS / 128, BB * NH);              // (16, 32)
    attn_kernel<<<ga, 128, smem_attn>>>(vmask, qmask, out);
}

// round 13
// speedup vs baseline: 1.0912x; 1.0912x over previous
#include <cuda_runtime.h>

#define NH 16
#define HD 64
#define BB 2
#define SS 2048
#define DD 1024
#define ND (NH*HD)          // 1024
#define BHSD (BB*NH*SS*HD)  // 4,194,304 elems per tensor

// scratch as TF32 bits, PRE-PERMUTED for attn fragment loads:
//   Q: [bh][s][slot(d)]  (pre-scaled by 0.125*log2e)
//   K: [bh][s][slot(d)]
//   V: [bh][d][g*64 + slot(s%64)]  (transposed, per-64-key-group permuted)
// slot(c) = (c&3)*16 + (c>>3)*2 + ((c>>2)&1)
__device__ unsigned g_scr[3][BHSD];

#define QSC 0.18033688011112042f          /* 0.125 * log2(e) */
#define CMSK 1.4426950408889634e10f       /* 1e10 * log2(e) */
#define PSLOT(c) ((((c) & 3) << 4) + (((c) >> 3) << 1) + (((c) >> 2) & 1))

__device__ __forceinline__ unsigned f2tf(float x) {
    unsigned r; asm("cvt.rna.tf32.f32 %0, %1;" : "=r"(r) : "f"(x)); return r;
}
__device__ __forceinline__ float ex2(float x) {
    float r; asm("ex2.approx.f32 %0, %1;" : "=f"(r) : "f"(x)); return r;
}

__device__ __forceinline__ void mma8(float* c, const unsigned* a, const unsigned* b) {
    asm volatile(
        "mma.sync.aligned.m16n8k8.row.col.f32.tf32.tf32.f32 "
        "{%0,%1,%2,%3}, {%4,%5,%6,%7}, {%8,%9}, {%0,%1,%2,%3};\n"
        : "+f"(c[0]), "+f"(c[1]), "+f"(c[2]), "+f"(c[3])
        : "r"(a[0]), "r"(a[1]), "r"(a[2]), "r"(a[3]), "r"(b[0]), "r"(b[1]));
}

__device__ __forceinline__ void split2(float x, unsigned& h, unsigned& l) {
    unsigned hb = f2tf(x);
    float r = x - __uint_as_float(hb);
    h = hb; l = f2tf(r);
}

__device__ __forceinline__ void cp16(unsigned smem_addr, const void* gptr) {
    asm volatile("cp.async.cg.shared.global [%0], [%1], 16;"
                 :: "r"(smem_addr), "l"(gptr));
}
#define CP_COMMIT() asm volatile("cp.async.commit_group;" ::: "memory")
#define CP_WAIT0()  asm volatile("cp.async.wait_group 0;" ::: "memory")

// ---------------------------------------------------------------------------
// Projections: A[4096,1024] @ W[1024,1024] -> g_scr[z] as TF32 (permuted).
// 2-term split: (Ah + Al) @ tf32(W), split/cvt at fragment-load time.
// BM=128,BN=128,BK=16; 4 warps, warp tile 64x64. cp.async double buffer.
// ---------------------------------------------------------------------------
__global__ __launch_bounds__(128) void proj_kernel(
    const float* __restrict__ q, const float* __restrict__ k, const float* __restrict__ v,
    const float* __restrict__ Wq, const float* __restrict__ Wk, const float* __restrict__ Wv)
{
    __shared__ float sbuf[2 * 4672];     // per stage: A[128][20] + W[16][132]

    const int which = blockIdx.z;
    const float* A = which == 0 ? q : (which == 1 ? k : v);
    const float* W = which == 0 ? Wq : (which == 1 ? Wk : Wv);

    const int tid = threadIdx.x;
    const int lane = tid & 31;
    const int w = tid >> 5;
    const int gid = lane >> 2, tig = lane & 3;
    const int wm = w >> 1, wn = w & 1;   // 2x2 warp grid, warp tile 64x64
    const int m0 = blockIdx.y * 128, n0 = blockIdx.x * 128;

    const int am = tid;
    const int wr = tid >> 4;
    const int wc = (tid & 15) * 8;

    const float* Ap = A + (size_t)(m0 + am) * DD;
    const float* Wp = W + (size_t)wr * ND + n0 + wc;

    unsigned sb = (unsigned)__cvta_generic_to_shared(sbuf);
    unsigned a_dst[2], w_dst0[2], w_dst1[2];
    #pragma unroll
    for (int s = 0; s < 2; s++) {
        unsigned base = sb + s * 4672 * 4;
        a_dst[s]  = base + (am * 20) * 4;
        w_dst0[s] = base + (2560 + wr * 132 + wc) * 4;
        w_dst1[s] = base + (2560 + (wr + 8) * 132 + wc) * 4;
    }

    float C[4][8][4];
    #pragma unroll
    for (int i = 0; i < 4; i++)
        #pragma unroll
        for (int j = 0; j < 8; j++)
            #pragma unroll
            for (int e = 0; e < 4; e++) C[i][j][e] = 0.f;

    {
        cp16(a_dst[0],      Ap);
        cp16(a_dst[0] + 16, Ap + 4);
        cp16(a_dst[0] + 32, Ap + 8);
        cp16(a_dst[0] + 48, Ap + 12);
        cp16(w_dst0[0],      Wp);
        cp16(w_dst0[0] + 16, Wp + 4);
        cp16(w_dst1[0],      Wp + (size_t)8 * ND);
        cp16(w_dst1[0] + 16, Wp + (size_t)8 * ND + 4);
        CP_COMMIT();
    }

    const int NIT = DD / 16;             // 64
    for (int it = 0; it < NIT; it++) {
        CP_WAIT0();
        __syncthreads();

        if (it + 1 < NIT) {
            const int nk = (it + 1) * 16;
            const int s = (it + 1) & 1;
            cp16(a_dst[s],      Ap + nk);
            cp16(a_dst[s] + 16, Ap + nk + 4);
            cp16(a_dst[s] + 32, Ap + nk + 8);
            cp16(a_dst[s] + 48, Ap + nk + 12);
            cp16(w_dst0[s],      Wp + (size_t)nk * ND);
            cp16(w_dst0[s] + 16, Wp + (size_t)nk * ND + 4);
            cp16(w_dst1[s],      Wp + (size_t)(nk + 8) * ND);
            cp16(w_dst1[s] + 16, Wp + (size_t)(nk + 8) * ND + 4);
            CP_COMMIT();
        }

        const float* Ab = sbuf + (it & 1) * 4672;
        const float* Wb = Ab + 2560;

        #pragma unroll
        for (int ks = 0; ks < 2; ks++) {
            const int kk = ks * 8;
            unsigned ah[4][4], al[4][4], bh[8][2];
            #pragma unroll
            for (int mf = 0; mf < 4; mf++) {
                int r = wm * 64 + mf * 16 + gid;
                split2(Ab[r * 20 + kk + tig],           ah[mf][0], al[mf][0]);
                split2(Ab[(r + 8) * 20 + kk + tig],     ah[mf][1], al[mf][1]);
                split2(Ab[r * 20 + kk + tig + 4],       ah[mf][2], al[mf][2]);
                split2(Ab[(r + 8) * 20 + kk + tig + 4], ah[mf][3], al[mf][3]);
            }
            #pragma unroll
            for (int nf = 0; nf < 8; nf++) {
                int c = wn * 64 + nf * 8 + gid;
                bh[nf][0] = f2tf(Wb[(kk + tig) * 132 + c]);
                bh[nf][1] = f2tf(Wb[(kk + tig + 4) * 132 + c]);
            }
            #pragma unroll
            for (int mf = 0; mf < 4; mf++)
                #pragma unroll
                for (int nf = 0; nf < 8; nf++) {
                    mma8(C[mf][nf], al[mf], bh[nf]);
                    mma8(C[mf][nf], ah[mf], bh[nf]);
                }
        }
    }

    unsigned* out = g_scr[which];
    if (which < 2) {
        // Q (pre-scaled) / K: [bh][s][slot(d)], scalar stores into permuted slots
        const float sc = (which == 0) ? QSC : 1.0f;
        #pragma unroll
        for (int mf = 0; mf < 4; mf++) {
            int R = m0 + wm * 64 + mf * 16 + gid;
            #pragma unroll
            for (int half = 0; half < 2; half++) {
                int Rr = R + half * 8;
                int bb = Rr >> 11;
                int s  = Rr & 2047;
                #pragma unroll
                for (int nf = 0; nf < 8; nf++) {
                    int Cc = n0 + wn * 64 + nf * 8 + tig * 2;
                    int hh = Cc >> 6, dd = Cc & 63;
                    unsigned* base = out + ((size_t)(bb * NH + hh) * SS + s) * HD;
                    base[PSLOT(dd)]     = f2tf(C[mf][nf][half * 2 + 0] * sc);
                    base[PSLOT(dd + 1)] = f2tf(C[mf][nf][half * 2 + 1] * sc);
                }
            }
        }
    } else {
        // V: [bh][d][group*64 + slot(s%64)] via smem staging
        float (*stg)[129] = (float(*)[129])sbuf;
        #pragma unroll
        for (int ch = 0; ch < 2; ch++) {
            __syncthreads();
            if (wm == ch) {
                #pragma unroll
                for (int mf = 0; mf < 4; mf++)
                    #pragma unroll
                    for (int half = 0; half < 2; half++) {
                        int rr = mf * 16 + half * 8 + gid;
                        #pragma unroll
                        for (int nf = 0; nf < 8; nf++) {
                            int cc = wn * 64 + nf * 8 + tig * 2;
                            stg[rr][cc]     = C[mf][nf][half * 2 + 0];
                            stg[rr][cc + 1] = C[mf][nf][half * 2 + 1];
                        }
                    }
            }
            __syncthreads();
            const int base_s = m0 + ch * 64;      // 64-aligned group base
            const int bb = base_s >> 11;
            const int s_loc = base_s & 2047;
            #pragma unroll
            for (int cc = 0; cc < 32; cc++) {
                int c = w * 32 + cc;
                int hh = (n0 + c) >> 6, dd = (n0 + c) & 63;
                unsigned* dst = out + ((size_t)(bb * NH + hh) * HD + dd) * SS + s_loc;
                #pragma unroll
                for (int sg = 0; sg < 2; sg++) {
                    int s = sg * 32 + lane;       // 0..63 within group
                    dst[PSLOT(s)] = f2tf(stg[s][c]);
                }
            }
        }
    }
}

// ---------------------------------------------------------------------------
// Flash attention, TF32 mma. 128-q tile, 4 warps x 32 rows (two m-frags
// share K/V fragment loads). P in registers. K/V double-buffered via
// cp.async straight into the pre-permuted layout (no LDG/STS staging).
// ---------------------------------------------------------------------------
__global__ __launch_bounds__(128, 2) void attn_kernel(
    const int* __restrict__ v_mask, const int* __restrict__ q_mask,
    float* __restrict__ out)
{
    extern __shared__ unsigned smu[];
    unsigned* Qp = smu;                  // [128][68]
    unsigned* KV = smu + 128 * 68;       // [2][ K:64*68 | V:64*68 ]
    float* kbb  = (float*)(KV + 4 * 64 * 68);   // [2][64]

    const int tid = threadIdx.x;
    const int lane = tid & 31;
    const int w = tid >> 5;
    const int gid = lane >> 2, tig = lane & 3;
    const int qt = gridDim.x - 1 - blockIdx.x;
    const int bh = blockIdx.y;
    const int b = bh >> 4, h = bh & 15;
    const int q0 = qt * 128;
    const int kt_hi = (q0 + 127) >> 6;
    const int NT = SS / 64;

    const unsigned* Qg = g_scr[0] + (size_t)bh * SS * HD;
    const unsigned* Kg = g_scr[1] + (size_t)bh * SS * HD;
    const unsigned* Vg = g_scr[2] + (size_t)bh * HD * SS;

    unsigned sb = (unsigned)__cvta_generic_to_shared(smu);
    const int llr = tid >> 1;            // K/V row 0..63
    const int lhalf = (tid & 1) * 32;    // word offset 0 or 32 within row
    unsigned kdst[2], vdst[2];
    #pragma unroll
    for (int s = 0; s < 2; s++) {
        unsigned base = sb + (128 * 68 + s * 2 * 64 * 68) * 4;
        kdst[s] = base + (llr * 68 + lhalf) * 4;
        vdst[s] = base + (64 * 68 + llr * 68 + lhalf) * 4;
    }

    // prologue: Q tile + K/V tile 0 + kb(0)
    {
        unsigned qdst = sb + (tid * 68) * 4;
        const unsigned* qsrc = Qg + (size_t)(q0 + tid) * HD;
        #pragma unroll
        for (int j = 0; j < 16; j++)
            cp16(qdst + j * 16, qsrc + j * 4);
        const unsigned* ksrc = Kg + (size_t)llr * HD + lhalf;
        const unsigned* vsrc = Vg + (size_t)llr * SS + lhalf;
        #pragma unroll
        for (int j = 0; j < 8; j++) {
            cp16(kdst[0] + j * 16, ksrc + j * 4);
            cp16(vdst[0] + j * 16, vsrc + j * 4);
        }
        if (tid < 64) kbb[tid] = v_mask[b * SS + tid] ? 0.f : -CMSK;
        CP_COMMIT();
    }

    const float NEG_INF = __int_as_float(0xff800000);
    float m[2][2] = {{NEG_INF, NEG_INF}, {NEG_INF, NEG_INF}};
    float l[2][2] = {{0.f, 0.f}, {0.f, 0.f}};
    float acc[2][8][4];
    #pragma unroll
    for (int mf = 0; mf < 2; mf++)
        #pragma unroll
        for (int of = 0; of < 8; of++)
            #pragma unroll
            for (int e = 0; e < 4; e++) acc[mf][of][e] = 0.f;

    int deg = 0;
    const int rq = w * 32 + gid;
    const int koff = ((gid >> 1) + ((gid & 1) << 2)) * 68 + tig * 16;
    const int qoff0 = rq * 68 + tig * 16;
    const int qoff1 = (rq + 8) * 68 + tig * 16;
    const int qoff2 = (rq + 16) * 68 + tig * 16;
    const int qoff3 = (rq + 24) * 68 + tig * 16;

    float rkb = 0.f;

    for (int kt = 0; kt < NT; kt++) {
        if (kt > kt_hi && !deg) { CP_WAIT0(); break; }
        const int k0 = kt * 64;
        const int cur = kt & 1, nxt = cur ^ 1;
        const unsigned* Kp = KV + cur * (2 * 64 * 68);
        const unsigned* Vp = Kp + 64 * 68;
        const float* kb = kbb + cur * 64;
        const bool pf = (kt + 1 < NT);

        CP_WAIT0();
        __syncthreads();

        // ---- QK: both m-frags share each K fragment load ----
        float sc[2][8][4];
        #pragma unroll
        for (int mf = 0; mf < 2; mf++)
            #pragma unroll
            for (int nf = 0; nf < 8; nf++)
                #pragma unroll
                for (int e = 0; e < 4; e++) sc[mf][nf][e] = 0.f;

        #pragma unroll
        for (int j = 0; j < 4; j++) {
            uint4 a0 = *(const uint4*)&Qp[qoff0 + j * 4];
            uint4 a1 = *(const uint4*)&Qp[qoff1 + j * 4];
            uint4 a2 = *(const uint4*)&Qp[qoff2 + j * 4];
            uint4 a3 = *(const uint4*)&Qp[qoff3 + j * 4];
            unsigned Ae0[4] = {a0.x, a1.x, a0.y, a1.y};
            unsigned Ao0[4] = {a0.z, a1.z, a0.w, a1.w};
            unsigned Ae1[4] = {a2.x, a3.x, a2.y, a3.y};
            unsigned Ao1[4] = {a2.z, a3.z, a2.w, a3.w};
            #pragma unroll
            for (int nf = 0; nf < 8; nf++) {
                uint4 bv = *(const uint4*)&Kp[nf * 544 + koff + j * 4];
                unsigned Be[2] = {bv.x, bv.y};
                unsigned Bo[2] = {bv.z, bv.w};
                mma8(sc[0][nf], Ae0, Be);
                mma8(sc[0][nf], Ao0, Bo);
                mma8(sc[1][nf], Ae1, Be);
                mma8(sc[1][nf], Ao1, Bo);
            }
        }

        // ---- issue cp.async for tile kt+1 into the other buffer ----
        if (pf) {
            const int nk0 = k0 + 64;
            const unsigned* ksrc = Kg + (size_t)(nk0 + llr) * HD + lhalf;
            const unsigned* vsrc = Vg + (size_t)llr * SS + nk0 + lhalf;
            #pragma unroll
            for (int j = 0; j < 8; j++) {
                cp16(kdst[nxt] + j * 16, ksrc + j * 4);
                cp16(vdst[nxt] + j * 16, vsrc + j * 4);
            }
            CP_COMMIT();
            if (tid < 64) rkb = v_mask[b * SS + nk0 + tid] ? 0.f : -CMSK;
        }

        // ---- mask + online softmax ----
        float kb0[8], kb1[8];
        #pragma unroll
        for (int nf = 0; nf < 8; nf++) {
            kb0[nf] = kb[nf * 8 + tig];
            kb1[nf] = kb[nf * 8 + tig + 4];
        }
        #pragma unroll
        for (int mf = 0; mf < 2; mf++)
            #pragma unroll
            for (int i = 0; i < 2; i++) {
                int qg = q0 + rq + mf * 16 + 8 * i;
                float mx = NEG_INF;
                #pragma unroll
                for (int nf = 0; nf < 8; nf++) {
                    float s0 = sc[mf][nf][2 * i + 0] + kb0[nf];
                    float s1 = sc[mf][nf][2 * i + 1] + kb1[nf];
                    if (k0 + nf * 8 + tig > qg)     s0 -= CMSK;
                    if (k0 + nf * 8 + tig + 4 > qg) s1 -= CMSK;
                    sc[mf][nf][2 * i + 0] = s0;
                    sc[mf][nf][2 * i + 1] = s1;
                    mx = fmaxf(mx, fmaxf(s0, s1));
                }
                mx = fmaxf(mx, __shfl_xor_sync(0xffffffffu, mx, 1));
                mx = fmaxf(mx, __shfl_xor_sync(0xffffffffu, mx, 2));
                float nm = fmaxf(m[mf][i], mx);
                float rs = 0.f;
                #pragma unroll
                for (int nf = 0; nf < 8; nf++)
                    #pragma unroll
                    for (int jj = 0; jj < 2; jj++) {
                        float p = ex2(sc[mf][nf][2 * i + jj] - nm);
                        rs += p;
                        sc[mf][nf][2 * i + jj] = __uint_as_float(f2tf(p));
                    }
                rs += __shfl_xor_sync(0xffffffffu, rs, 1);
                rs += __shfl_xor_sync(0xffffffffu, rs, 2);
                float alpha = ex2(m[mf][i] - nm);
                l[mf][i] = l[mf][i] * alpha + rs;
                m[mf][i] = nm;
                #pragma unroll
                for (int of = 0; of < 8; of++) {
                    acc[mf][of][2 * i + 0] *= alpha;
                    acc[mf][of][2 * i + 1] *= alpha;
                }
            }

        // ---- PV: both m-frags share each V fragment load ----
        #pragma unroll
        for (int of = 0; of < 8; of++) {
            const unsigned* vb = &Vp[(of * 8 + gid) * 68 + tig * 16];
            uint4 ww[4];
            ww[0] = *(const uint4*)(vb);
            ww[1] = *(const uint4*)(vb + 4);
            ww[2] = *(const uint4*)(vb + 8);
            ww[3] = *(const uint4*)(vb + 12);
            #pragma unroll
            for (int nf = 0; nf < 8; nf++) {
                unsigned Bf[2];
                if ((nf & 1) == 0) { Bf[0] = ((const unsigned*)&ww[nf >> 1])[0];
                                     Bf[1] = ((const unsigned*)&ww[nf >> 1])[1]; }
                else               { Bf[0] = ((const unsigned*)&ww[nf >> 1])[2];
                                     Bf[1] = ((const unsigned*)&ww[nf >> 1])[3]; }
                #pragma unroll
                for (int mf = 0; mf < 2; mf++) {
                    unsigned Af[4] = {__float_as_uint(sc[mf][nf][0]), __float_as_uint(sc[mf][nf][2]),
                                      __float_as_uint(sc[mf][nf][1]), __float_as_uint(sc[mf][nf][3])};
                    mma8(acc[mf][of], Af, Bf);
                }
            }
        }

        // ---- kb for next tile ----
        if (pf && tid < 64) kbb[nxt * 64 + tid] = rkb;

        // ---- degenerate-row vote after the last causal tile ----
        if (kt == kt_hi)
            deg = __syncthreads_or((m[0][0] < -1e10f) || (m[0][1] < -1e10f) ||
                                   (m[1][0] < -1e10f) || (m[1][1] < -1e10f));
    }

    // epilogue
    #pragma unroll
    for (int mf = 0; mf < 2; mf++)
        #pragma unroll
        for (int i = 0; i < 2; i++) {
            int qg = q0 + rq + mf * 16 + 8 * i;
            float qm = (float)q_mask[b * SS + qg];
            float f = qm / l[mf][i];
            #pragma unroll
            for (int of = 0; of < 8; of++) {
                float2 o = make_float2(acc[mf][of][2 * i + 0] * f, acc[mf][of][2 * i + 1] * f);
                *(float2*)(out + ((size_t)b * SS + qg) * ND + h * HD + of * 8 + tig * 2) = o;
            }
        }
}

// ---------------------------------------------------------------------------
extern "C" void kernel_launch(void* const* d_in, const int* in_sizes, int n_in,
                              void* d_out, int out_size)
{
    const float* q  = (const float*)d_in[0];
    const float* k  = (const float*)d_in[1];
    const float* v  = (const float*)d_in[2];
    const int* vmask = (const int*)d_in[3];
    const int* qmask = (const int*)d_in[4];
    const float* Wq = (const float*)d_in[5];
    const float* Wk = (const float*)d_in[6];
    const float* Wv = (const float*)d_in[7];
    float* out = (float*)d_out;

    const int smem_attn = (128 * 68 + 4 * 64 * 68 + 2 * 64) * 4;   // 104,960 B
    cudaFuncSetAttribute(attn_kernel, cudaFuncAttributeMaxDynamicSharedMemorySize, smem_attn);

    dim3 gp(ND / 128, (BB * SS) / 128, 3);   // (8, 32, 3)
    proj_kernel<<<gp, 128>>>(q, k, v, Wq, Wk, Wv);

    dim3 ga(SS / 128, BB * NH);              // (16, 32)
    attn_kernel<<<ga, 128, smem_attn>>>(vmask, qmask, out);
}

// round 14
// speedup vs baseline: 1.3127x; 1.2030x over previous
#include <cuda_runtime.h>
#include <cuda_fp16.h>

#define NH 16
#define HD 64
#define BB 2
#define SS 2048
#define DD 1024
#define ND (NH*HD)          // 1024
#define BHSD (BB*NH*SS*HD)  // 4,194,304 elems per tensor

// scratch as TF32 bits, PRE-PERMUTED for attn fragment loads:
//   Q: [bh][s][slot(d)]  (pre-scaled by 0.125*log2e)
//   K: [bh][s][slot(d)]
//   V: [bh][d][g*64 + slot(s%64)]
// slot(c) = (c&3)*16 + (c>>3)*2 + ((c>>2)&1)
__device__ unsigned g_scr[3][BHSD];

#define QSC 0.18033688011112042f          /* 0.125 * log2(e) */
#define CMSK 1.4426950408889634e10f       /* 1e10 * log2(e) */
#define PSLOT(c) ((((c) & 3) << 4) + (((c) >> 3) << 1) + (((c) >> 2) & 1))

__device__ __forceinline__ unsigned f2tf(float x) {
    unsigned r; asm("cvt.rna.tf32.f32 %0, %1;" : "=r"(r) : "f"(x)); return r;
}
__device__ __forceinline__ float ex2(float x) {
    float r; asm("ex2.approx.f32 %0, %1;" : "=f"(r) : "f"(x)); return r;
}

// tf32 k8 mma (attention)
__device__ __forceinline__ void mma8(float* c, const unsigned* a, const unsigned* b) {
    asm volatile(
        "mma.sync.aligned.m16n8k8.row.col.f32.tf32.tf32.f32 "
        "{%0,%1,%2,%3}, {%4,%5,%6,%7}, {%8,%9}, {%0,%1,%2,%3};\n"
        : "+f"(c[0]), "+f"(c[1]), "+f"(c[2]), "+f"(c[3])
        : "r"(a[0]), "r"(a[1]), "r"(a[2]), "r"(a[3]), "r"(b[0]), "r"(b[1]));
}

// fp16 k16 mma (projections); C layout identical to tf32 k8
__device__ __forceinline__ void mmah(float* c, const unsigned* a, const unsigned* b) {
    asm volatile(
        "mma.sync.aligned.m16n8k16.row.col.f32.f16.f16.f32 "
        "{%0,%1,%2,%3}, {%4,%5,%6,%7}, {%8,%9}, {%0,%1,%2,%3};\n"
        : "+f"(c[0]), "+f"(c[1]), "+f"(c[2]), "+f"(c[3])
        : "r"(a[0]), "r"(a[1]), "r"(a[2]), "r"(a[3]), "r"(b[0]), "r"(b[1]));
}

// pack two f32 into f16x2 word: lo -> low half, hi -> high half
__device__ __forceinline__ unsigned packh2(float lo, float hi) {
    unsigned r; asm("cvt.rn.f16x2.f32 %0, %1, %2;" : "=r"(r) : "f"(hi), "f"(lo));
    return r;
}
// split a float2 (consecutive k) into fp16 hi word + fp16 lo-residual word
__device__ __forceinline__ void splith2(float2 x, unsigned& h, unsigned& l) {
    h = packh2(x.x, x.y);
    __half2 hh = *(__half2*)&h;
    float2 hf = __half22float2(hh);
    l = packh2(x.x - hf.x, x.y - hf.y);
}

__device__ __forceinline__ void cp16(unsigned smem_addr, const void* gptr) {
    asm volatile("cp.async.cg.shared.global [%0], [%1], 16;"
                 :: "r"(smem_addr), "l"(gptr));
}
#define CP_COMMIT() asm volatile("cp.async.commit_group;" ::: "memory")
#define CP_WAIT0()  asm volatile("cp.async.wait_group 0;" ::: "memory")

// ---------------------------------------------------------------------------
// Projections: A[4096,1024] @ W[1024,1024] -> g_scr[z] as TF32 (permuted).
// fp16 2-term split: (Ah + Al)_fp16 @ W_fp16, m16n8k16 mma => HALF the
// tensor cycles of the tf32 scheme. W single fp16 == W single tf32 error
// (both 10 explicit mantissa bits). BM=128,BN=128,BK=16; 4 warps, 64x64
// warp tiles; cp.async double buffer.
// ---------------------------------------------------------------------------
__global__ __launch_bounds__(128) void proj_kernel(
    const float* __restrict__ q, const float* __restrict__ k, const float* __restrict__ v,
    const float* __restrict__ Wq, const float* __restrict__ Wk, const float* __restrict__ Wv)
{
    __shared__ float sbuf[2 * 4672];     // per stage: A[128][20] + W[16][132]

    const int which = blockIdx.z;
    const float* A = which == 0 ? q : (which == 1 ? k : v);
    const float* W = which == 0 ? Wq : (which == 1 ? Wk : Wv);

    const int tid = threadIdx.x;
    const int lane = tid & 31;
    const int w = tid >> 5;
    const int gid = lane >> 2, tig = lane & 3;
    const int wm = w >> 1, wn = w & 1;   // 2x2 warp grid, warp tile 64x64
    const int m0 = blockIdx.y * 128, n0 = blockIdx.x * 128;

    const int am = tid;
    const int wr = tid >> 4;
    const int wc = (tid & 15) * 8;

    const float* Ap = A + (size_t)(m0 + am) * DD;
    const float* Wp = W + (size_t)wr * ND + n0 + wc;

    unsigned sb = (unsigned)__cvta_generic_to_shared(sbuf);
    unsigned a_dst[2], w_dst0[2], w_dst1[2];
    #pragma unroll
    for (int s = 0; s < 2; s++) {
        unsigned base = sb + s * 4672 * 4;
        a_dst[s]  = base + (am * 20) * 4;
        w_dst0[s] = base + (2560 + wr * 132 + wc) * 4;
        w_dst1[s] = base + (2560 + (wr + 8) * 132 + wc) * 4;
    }

    float C[4][8][4];
    #pragma unroll
    for (int i = 0; i < 4; i++)
        #pragma unroll
        for (int j = 0; j < 8; j++)
            #pragma unroll
            for (int e = 0; e < 4; e++) C[i][j][e] = 0.f;

    {
        cp16(a_dst[0],      Ap);
        cp16(a_dst[0] + 16, Ap + 4);
        cp16(a_dst[0] + 32, Ap + 8);
        cp16(a_dst[0] + 48, Ap + 12);
        cp16(w_dst0[0],      Wp);
        cp16(w_dst0[0] + 16, Wp + 4);
        cp16(w_dst1[0],      Wp + (size_t)8 * ND);
        cp16(w_dst1[0] + 16, Wp + (size_t)8 * ND + 4);
        CP_COMMIT();
    }

    const int NIT = DD / 16;             // 64
    for (int it = 0; it < NIT; it++) {
        CP_WAIT0();
        __syncthreads();

        if (it + 1 < NIT) {
            const int nk = (it + 1) * 16;
            const int s = (it + 1) & 1;
            cp16(a_dst[s],      Ap + nk);
            cp16(a_dst[s] + 16, Ap + nk + 4);
            cp16(a_dst[s] + 32, Ap + nk + 8);
            cp16(a_dst[s] + 48, Ap + nk + 12);
            cp16(w_dst0[s],      Wp + (size_t)nk * ND);
            cp16(w_dst0[s] + 16, Wp + (size_t)nk * ND + 4);
            cp16(w_dst1[s],      Wp + (size_t)(nk + 8) * ND);
            cp16(w_dst1[s] + 16, Wp + (size_t)(nk + 8) * ND + 4);
            CP_COMMIT();
        }

        const float* Ab = sbuf + (it & 1) * 4672;
        const float* Wb = Ab + 2560;

        // one k16 step per iteration
        unsigned ah[4][4], al[4][4], bw[8][2];
        #pragma unroll
        for (int mf = 0; mf < 4; mf++) {
            int r = wm * 64 + mf * 16 + gid;
            float2 x00 = *(const float2*)&Ab[r * 20 + 2 * tig];            // k=2t,2t+1
            float2 x10 = *(const float2*)&Ab[(r + 8) * 20 + 2 * tig];
            float2 x01 = *(const float2*)&Ab[r * 20 + 2 * tig + 8];        // k=2t+8,2t+9
            float2 x11 = *(const float2*)&Ab[(r + 8) * 20 + 2 * tig + 8];
            splith2(x00, ah[mf][0], al[mf][0]);
            splith2(x10, ah[mf][1], al[mf][1]);
            splith2(x01, ah[mf][2], al[mf][2]);
            splith2(x11, ah[mf][3], al[mf][3]);
        }
        #pragma unroll
        for (int nf = 0; nf < 8; nf++) {
            int c = wn * 64 + nf * 8 + gid;
            bw[nf][0] = packh2(Wb[(2 * tig) * 132 + c],     Wb[(2 * tig + 1) * 132 + c]);
            bw[nf][1] = packh2(Wb[(2 * tig + 8) * 132 + c], Wb[(2 * tig + 9) * 132 + c]);
        }
        #pragma unroll
        for (int mf = 0; mf < 4; mf++)
            #pragma unroll
            for (int nf = 0; nf < 8; nf++) {
                mmah(C[mf][nf], al[mf], bw[nf]);
                mmah(C[mf][nf], ah[mf], bw[nf]);
            }
    }

    unsigned* out = g_scr[which];
    if (which < 2) {
        const float sc = (which == 0) ? QSC : 1.0f;
        #pragma unroll
        for (int mf = 0; mf < 4; mf++) {
            int R = m0 + wm * 64 + mf * 16 + gid;
            #pragma unroll
            for (int half = 0; half < 2; half++) {
                int Rr = R + half * 8;
                int bb = Rr >> 11;
                int s  = Rr & 2047;
                #pragma unroll
                for (int nf = 0; nf < 8; nf++) {
                    int Cc = n0 + wn * 64 + nf * 8 + tig * 2;
                    int hh = Cc >> 6, dd = Cc & 63;
                    unsigned* base = out + ((size_t)(bb * NH + hh) * SS + s) * HD;
                    base[PSLOT(dd)]     = f2tf(C[mf][nf][half * 2 + 0] * sc);
                    base[PSLOT(dd + 1)] = f2tf(C[mf][nf][half * 2 + 1] * sc);
                }
            }
        }
    } else {
        // V: [bh][d][group*64 + slot(s%64)] via smem staging
        float (*stg)[129] = (float(*)[129])sbuf;
        #pragma unroll
        for (int ch = 0; ch < 2; ch++) {
            __syncthreads();
            if (wm == ch) {
                #pragma unroll
                for (int mf = 0; mf < 4; mf++)
                    #pragma unroll
                    for (int half = 0; half < 2; half++) {
                        int rr = mf * 16 + half * 8 + gid;
                        #pragma unroll
                        for (int nf = 0; nf < 8; nf++) {
                            int cc = wn * 64 + nf * 8 + tig * 2;
                            stg[rr][cc]     = C[mf][nf][half * 2 + 0];
                            stg[rr][cc + 1] = C[mf][nf][half * 2 + 1];
                        }
                    }
            }
            __syncthreads();
            const int base_s = m0 + ch * 64;
            const int bb = base_s >> 11;
            const int s_loc = base_s & 2047;
            #pragma unroll
            for (int cc = 0; cc < 32; cc++) {
                int c = w * 32 + cc;
                int hh = (n0 + c) >> 6, dd = (n0 + c) & 63;
                unsigned* dst = out + ((size_t)(bb * NH + hh) * HD + dd) * SS + s_loc;
                #pragma unroll
                for (int sg = 0; sg < 2; sg++) {
                    int s = sg * 32 + lane;
                    dst[PSLOT(s)] = f2tf(stg[s][c]);
                }
            }
        }
    }
}

// ---------------------------------------------------------------------------
// Flash attention (round-13, unchanged). TF32 mma. 128-q tile, 4 warps x
// 32 rows; P in registers; K/V double-buffered via cp.async into the
// pre-permuted layout.
// ---------------------------------------------------------------------------
__global__ __launch_bounds__(128, 2) void attn_kernel(
    const int* __restrict__ v_mask, const int* __restrict__ q_mask,
    float* __restrict__ out)
{
    extern __shared__ unsigned smu[];
    unsigned* Qp = smu;                  // [128][68]
    unsigned* KV = smu + 128 * 68;       // [2][ K:64*68 | V:64*68 ]
    float* kbb  = (float*)(KV + 4 * 64 * 68);   // [2][64]

    const int tid = threadIdx.x;
    const int lane = tid & 31;
    const int w = tid >> 5;
    const int gid = lane >> 2, tig = lane & 3;
    const int qt = gridDim.x - 1 - blockIdx.x;
    const int bh = blockIdx.y;
    const int b = bh >> 4, h = bh & 15;
    const int q0 = qt * 128;
    const int kt_hi = (q0 + 127) >> 6;
    const int NT = SS / 64;

    const unsigned* Qg = g_scr[0] + (size_t)bh * SS * HD;
    const unsigned* Kg = g_scr[1] + (size_t)bh * SS * HD;
    const unsigned* Vg = g_scr[2] + (size_t)bh * HD * SS;

    unsigned sb = (unsigned)__cvta_generic_to_shared(smu);
    const int llr = tid >> 1;
    const int lhalf = (tid & 1) * 32;
    unsigned kdst[2], vdst[2];
    #pragma unroll
    for (int s = 0; s < 2; s++) {
        unsigned base = sb + (128 * 68 + s * 2 * 64 * 68) * 4;
        kdst[s] = base + (llr * 68 + lhalf) * 4;
        vdst[s] = base + (64 * 68 + llr * 68 + lhalf) * 4;
    }

    {
        unsigned qdst = sb + (tid * 68) * 4;
        const unsigned* qsrc = Qg + (size_t)(q0 + tid) * HD;
        #pragma unroll
        for (int j = 0; j < 16; j++)
            cp16(qdst + j * 16, qsrc + j * 4);
        const unsigned* ksrc = Kg + (size_t)llr * HD + lhalf;
        const unsigned* vsrc = Vg + (size_t)llr * SS + lhalf;
        #pragma unroll
        for (int j = 0; j < 8; j++) {
            cp16(kdst[0] + j * 16, ksrc + j * 4);
            cp16(vdst[0] + j * 16, vsrc + j * 4);
        }
        if (tid < 64) kbb[tid] = v_mask[b * SS + tid] ? 0.f : -CMSK;
        CP_COMMIT();
    }

    const float NEG_INF = __int_as_float(0xff800000);
    float m[2][2] = {{NEG_INF, NEG_INF}, {NEG_INF, NEG_INF}};
    float l[2][2] = {{0.f, 0.f}, {0.f, 0.f}};
    float acc[2][8][4];
    #pragma unroll
    for (int mf = 0; mf < 2; mf++)
        #pragma unroll
        for (int of = 0; of < 8; of++)
            #pragma unroll
            for (int e = 0; e < 4; e++) acc[mf][of][e] = 0.f;

    int deg = 0;
    const int rq = w * 32 + gid;
    const int koff = ((gid >> 1) + ((gid & 1) << 2)) * 68 + tig * 16;
    const int qoff0 = rq * 68 + tig * 16;
    const int qoff1 = (rq + 8) * 68 + tig * 16;
    const int qoff2 = (rq + 16) * 68 + tig * 16;
    const int qoff3 = (rq + 24) * 68 + tig * 16;

    float rkb = 0.f;

    for (int kt = 0; kt < NT; kt++) {
        if (kt > kt_hi && !deg) { CP_WAIT0(); break; }
        const int k0 = kt * 64;
        const int cur = kt & 1, nxt = cur ^ 1;
        const unsigned* Kp = KV + cur * (2 * 64 * 68);
        const unsigned* Vp = Kp + 64 * 68;
        const float* kb = kbb + cur * 64;
        const bool pf = (kt + 1 < NT);

        CP_WAIT0();
        __syncthreads();

        float sc[2][8][4];
        #pragma unroll
        for (int mf = 0; mf < 2; mf++)
            #pragma unroll
            for (int nf = 0; nf < 8; nf++)
                #pragma unroll
                for (int e = 0; e < 4; e++) sc[mf][nf][e] = 0.f;

        #pragma unroll
        for (int j = 0; j < 4; j++) {
            uint4 a0 = *(const uint4*)&Qp[qoff0 + j * 4];
            uint4 a1 = *(const uint4*)&Qp[qoff1 + j * 4];
            uint4 a2 = *(const uint4*)&Qp[qoff2 + j * 4];
            uint4 a3 = *(const uint4*)&Qp[qoff3 + j * 4];
            unsigned Ae0[4] = {a0.x, a1.x, a0.y, a1.y};
            unsigned Ao0[4] = {a0.z, a1.z, a0.w, a1.w};
            unsigned Ae1[4] = {a2.x, a3.x, a2.y, a3.y};
            unsigned Ao1[4] = {a2.z, a3.z, a2.w, a3.w};
            #pragma unroll
            for (int nf = 0; nf < 8; nf++) {
                uint4 bv = *(const uint4*)&Kp[nf * 544 + koff + j * 4];
                unsigned Be[2] = {bv.x, bv.y};
                unsigned Bo[2] = {bv.z, bv.w};
                mma8(sc[0][nf], Ae0, Be);
                mma8(sc[0][nf], Ao0, Bo);
                mma8(sc[1][nf], Ae1, Be);
                mma8(sc[1][nf], Ao1, Bo);
            }
        }

        if (pf) {
            const int nk0 = k0 + 64;
            const unsigned* ksrc = Kg + (size_t)(nk0 + llr) * HD + lhalf;
            const unsigned* vsrc = Vg + (size_t)llr * SS + nk0 + lhalf;
            #pragma unroll
            for (int j = 0; j < 8; j++) {
                cp16(kdst[nxt] + j * 16, ksrc + j * 4);
                cp16(vdst[nxt] + j * 16, vsrc + j * 4);
            }
            CP_COMMIT();
            if (tid < 64) rkb = v_mask[b * SS + nk0 + tid] ? 0.f : -CMSK;
        }

        float kb0[8], kb1[8];
        #pragma unroll
        for (int nf = 0; nf < 8; nf++) {
            kb0[nf] = kb[nf * 8 + tig];
            kb1[nf] = kb[nf * 8 + tig + 4];
        }
        #pragma unroll
        for (int mf = 0; mf < 2; mf++)
            #pragma unroll
            for (int i = 0; i < 2; i++) {
                int qg = q0 + rq + mf * 16 + 8 * i;
                float mx = NEG_INF;
                #pragma unroll
                for (int nf = 0; nf < 8; nf++) {
                    float s0 = sc[mf][nf][2 * i + 0] + kb0[nf];
                    float s1 = sc[mf][nf][2 * i + 1] + kb1[nf];
                    if (k0 + nf * 8 + tig > qg)     s0 -= CMSK;
                    if (k0 + nf * 8 + tig + 4 > qg) s1 -= CMSK;
                    sc[mf][nf][2 * i + 0] = s0;
                    sc[mf][nf][2 * i + 1] = s1;
                    mx = fmaxf(mx, fmaxf(s0, s1));
                }
                mx = fmaxf(mx, __shfl_xor_sync(0xffffffffu, mx, 1));
                mx = fmaxf(mx, __shfl_xor_sync(0xffffffffu, mx, 2));
                float nm = fmaxf(m[mf][i], mx);
                float rs = 0.f;
                #pragma unroll
                for (int nf = 0; nf < 8; nf++)
                    #pragma unroll
                    for (int jj = 0; jj < 2; jj++) {
                        float p = ex2(sc[mf][nf][2 * i + jj] - nm);
                        rs += p;
                        sc[mf][nf][2 * i + jj] = __uint_as_float(f2tf(p));
                    }
                rs += __shfl_xor_sync(0xffffffffu, rs, 1);
                rs += __shfl_xor_sync(0xffffffffu, rs, 2);
                float alpha = ex2(m[mf][i] - nm);
                l[mf][i] = l[mf][i] * alpha + rs;
                m[mf][i] = nm;
                #pragma unroll
                for (int of = 0; of < 8; of++) {
                    acc[mf][of][2 * i + 0] *= alpha;
                    acc[mf][of][2 * i + 1] *= alpha;
                }
            }

        #pragma unroll
        for (int of = 0; of < 8; of++) {
            const unsigned* vb = &Vp[(of * 8 + gid) * 68 + tig * 16];
            uint4 ww[4];
            ww[0] = *(const uint4*)(vb);
            ww[1] = *(const uint4*)(vb + 4);
            ww[2] = *(const uint4*)(vb + 8);
            ww[3] = *(const uint4*)(vb + 12);
            #pragma unroll
            for (int nf = 0; nf < 8; nf++) {
                unsigned Bf[2];
                if ((nf & 1) == 0) { Bf[0] = ((const unsigned*)&ww[nf >> 1])[0];
                                     Bf[1] = ((const unsigned*)&ww[nf >> 1])[1]; }
                else               { Bf[0] = ((const unsigned*)&ww[nf >> 1])[2];
                                     Bf[1] = ((const unsigned*)&ww[nf >> 1])[3]; }
                #pragma unroll
                for (int mf = 0; mf < 2; mf++) {
                    unsigned Af[4] = {__float_as_uint(sc[mf][nf][0]), __float_as_uint(sc[mf][nf][2]),
                                      __float_as_uint(sc[mf][nf][1]), __float_as_uint(sc[mf][nf][3])};
                    mma8(acc[mf][of], Af, Bf);
                }
            }
        }

        if (pf && tid < 64) kbb[nxt * 64 + tid] = rkb;

        if (kt == kt_hi)
            deg = __syncthreads_or((m[0][0] < -1e10f) || (m[0][1] < -1e10f) ||
                                   (m[1][0] < -1e10f) || (m[1][1] < -1e10f));
    }

    #pragma unroll
    for (int mf = 0; mf < 2; mf++)
        #pragma unroll
        for (int i = 0; i < 2; i++) {
            int qg = q0 + rq + mf * 16 + 8 * i;
            float qm = (float)q_mask[b * SS + qg];
            float f = qm / l[mf][i];
            #pragma unroll
            for (int of = 0; of < 8; of++) {
                float2 o = make_float2(acc[mf][of][2 * i + 0] * f, acc[mf][of][2 * i + 1] * f);
                *(float2*)(out + ((size_t)b * SS + qg) * ND + h * HD + of * 8 + tig * 2) = o;
            }
        }
}

// ---------------------------------------------------------------------------
extern "C" void kernel_launch(void* const* d_in, const int* in_sizes, int n_in,
                              void* d_out, int out_size)
{
    const float* q  = (const float*)d_in[0];
    const float* k  = (const float*)d_in[1];
    const float* v  = (const float*)d_in[2];
    const int* vmask = (const int*)d_in[3];
    const int* qmask = (const int*)d_in[4];
    const float* Wq = (const float*)d_in[5];
    const float* Wk = (const float*)d_in[6];
    const float* Wv = (const float*)d_in[7];
    float* out = (float*)d_out;

    const int smem_attn = (128 * 68 + 4 * 64 * 68 + 2 * 64) * 4;   // 104,960 B
    cudaFuncSetAttribute(attn_kernel, cudaFuncAttributeMaxDynamicSharedMemorySize, smem_attn);

    dim3 gp(ND / 128, (BB * SS) / 128, 3);   // (8, 32, 3)
    proj_kernel<<<gp, 128>>>(q, k, v, Wq, Wk, Wv);

    dim3 ga(SS / 128, BB * NH);              // (16, 32)
    attn_kernel<<<ga, 128, smem_attn>>>(vmask, qmask, out);
}

// round 15
// speedup vs baseline: 1.7691x; 1.3476x over previous
#include <cuda_runtime.h>
#include <cuda_fp16.h>

#define NH 16
#define HD 64
#define BB 2
#define SS 2048
#define DD 1024
#define ND (NH*HD)          // 1024
#define BHSD (BB*NH*SS*HD)  // sizing only (half used now)

// scratch as fp16x2 words, PRE-PERMUTED for attn fragment loads:
//   Q: [bh][s][32 words, slot16 order], word w = d(2w,2w+1), pre-scaled by QSC
//   K: [bh][s][32 words, slot16 order]  (natural key row order)
//   V: [bh][d][SS/2 words], per-64-key group: word u = keys (pi(2u), pi(2u+1)),
//      stored at slot16(u); pi(x) = (x&~7)|((x>>1)&3)|((x&1)<<2)
// slot16(w) = (w&3)*8 + (w>>3)*2 + ((w>>2)&1)
__device__ unsigned g_scr[3][BHSD];

#define QSC 0.18033688011112042f          /* 0.125 * log2(e) */
#define CMSK 1.4426950408889634e10f       /* 1e10 * log2(e) */
#define SLOT16(w) ((((w) & 3) << 3) + (((w) >> 3) << 1) + (((w) >> 2) & 1))

__device__ __forceinline__ float ex2(float x) {
    float r; asm("ex2.approx.f32 %0, %1;" : "=f"(r) : "f"(x)); return r;
}

// fp16 k16 mma; C layout == tf32 k8 (HW-validated in round 14)
__device__ __forceinline__ void mmah(float* c, const unsigned* a, const unsigned* b) {
    asm volatile(
        "mma.sync.aligned.m16n8k16.row.col.f32.f16.f16.f32 "
        "{%0,%1,%2,%3}, {%4,%5,%6,%7}, {%8,%9}, {%0,%1,%2,%3};\n"
        : "+f"(c[0]), "+f"(c[1]), "+f"(c[2]), "+f"(c[3])
        : "r"(a[0]), "r"(a[1]), "r"(a[2]), "r"(a[3]), "r"(b[0]), "r"(b[1]));
}

__device__ __forceinline__ unsigned packh2(float lo, float hi) {
    unsigned r; asm("cvt.rn.f16x2.f32 %0, %1, %2;" : "=r"(r) : "f"(hi), "f"(lo));
    return r;
}
__device__ __forceinline__ void splith2(float2 x, unsigned& h, unsigned& l) {
    h = packh2(x.x, x.y);
    __half2 hh = *(__half2*)&h;
    float2 hf = __half22float2(hh);
    l = packh2(x.x - hf.x, x.y - hf.y);
}

__device__ __forceinline__ void cp16(unsigned smem_addr, const void* gptr) {
    asm volatile("cp.async.cg.shared.global [%0], [%1], 16;"
                 :: "r"(smem_addr), "l"(gptr));
}
#define CP_COMMIT() asm volatile("cp.async.commit_group;" ::: "memory")
#define CP_WAIT0()  asm volatile("cp.async.wait_group 0;" ::: "memory")

// ---------------------------------------------------------------------------
// Projections (round-14 mainloop, fp16 epilogues): A @ W -> g_scr as fp16x2.
// ---------------------------------------------------------------------------
__global__ __launch_bounds__(128) void proj_kernel(
    const float* __restrict__ q, const float* __restrict__ k, const float* __restrict__ v,
    const float* __restrict__ Wq, const float* __restrict__ Wk, const float* __restrict__ Wv)
{
    __shared__ float sbuf[2 * 4672];     // per stage: A[128][20] + W[16][132]

    const int which = blockIdx.z;
    const float* A = which == 0 ? q : (which == 1 ? k : v);
    const float* W = which == 0 ? Wq : (which == 1 ? Wk : Wv);

    const int tid = threadIdx.x;
    const int lane = tid & 31;
    const int w = tid >> 5;
    const int gid = lane >> 2, tig = lane & 3;
    const int wm = w >> 1, wn = w & 1;
    const int m0 = blockIdx.y * 128, n0 = blockIdx.x * 128;

    const int am = tid;
    const int wr = tid >> 4;
    const int wc = (tid & 15) * 8;

    const float* Ap = A + (size_t)(m0 + am) * DD;
    const float* Wp = W + (size_t)wr * ND + n0 + wc;

    unsigned sb = (unsigned)__cvta_generic_to_shared(sbuf);
    unsigned a_dst[2], w_dst0[2], w_dst1[2];
    #pragma unroll
    for (int s = 0; s < 2; s++) {
        unsigned base = sb + s * 4672 * 4;
        a_dst[s]  = base + (am * 20) * 4;
        w_dst0[s] = base + (2560 + wr * 132 + wc) * 4;
        w_dst1[s] = base + (2560 + (wr + 8) * 132 + wc) * 4;
    }

    float C[4][8][4];
    #pragma unroll
    for (int i = 0; i < 4; i++)
        #pragma unroll
        for (int j = 0; j < 8; j++)
            #pragma unroll
            for (int e = 0; e < 4; e++) C[i][j][e] = 0.f;

    {
        cp16(a_dst[0],      Ap);
        cp16(a_dst[0] + 16, Ap + 4);
        cp16(a_dst[0] + 32, Ap + 8);
        cp16(a_dst[0] + 48, Ap + 12);
        cp16(w_dst0[0],      Wp);
        cp16(w_dst0[0] + 16, Wp + 4);
        cp16(w_dst1[0],      Wp + (size_t)8 * ND);
        cp16(w_dst1[0] + 16, Wp + (size_t)8 * ND + 4);
        CP_COMMIT();
    }

    const int NIT = DD / 16;
    for (int it = 0; it < NIT; it++) {
        CP_WAIT0();
        __syncthreads();

        if (it + 1 < NIT) {
            const int nk = (it + 1) * 16;
            const int s = (it + 1) & 1;
            cp16(a_dst[s],      Ap + nk);
            cp16(a_dst[s] + 16, Ap + nk + 4);
            cp16(a_dst[s] + 32, Ap + nk + 8);
            cp16(a_dst[s] + 48, Ap + nk + 12);
            cp16(w_dst0[s],      Wp + (size_t)nk * ND);
            cp16(w_dst0[s] + 16, Wp + (size_t)nk * ND + 4);
            cp16(w_dst1[s],      Wp + (size_t)(nk + 8) * ND);
            cp16(w_dst1[s] + 16, Wp + (size_t)(nk + 8) * ND + 4);
            CP_COMMIT();
        }

        const float* Ab = sbuf + (it & 1) * 4672;
        const float* Wb = Ab + 2560;

        unsigned ah[4][4], al[4][4], bw[8][2];
        #pragma unroll
        for (int mf = 0; mf < 4; mf++) {
            int r = wm * 64 + mf * 16 + gid;
            float2 x00 = *(const float2*)&Ab[r * 20 + 2 * tig];
            float2 x10 = *(const float2*)&Ab[(r + 8) * 20 + 2 * tig];
            float2 x01 = *(const float2*)&Ab[r * 20 + 2 * tig + 8];
            float2 x11 = *(const float2*)&Ab[(r + 8) * 20 + 2 * tig + 8];
            splith2(x00, ah[mf][0], al[mf][0]);
            splith2(x10, ah[mf][1], al[mf][1]);
            splith2(x01, ah[mf][2], al[mf][2]);
            splith2(x11, ah[mf][3], al[mf][3]);
        }
        #pragma unroll
        for (int nf = 0; nf < 8; nf++) {
            int c = wn * 64 + nf * 8 + gid;
            bw[nf][0] = packh2(Wb[(2 * tig) * 132 + c],     Wb[(2 * tig + 1) * 132 + c]);
            bw[nf][1] = packh2(Wb[(2 * tig + 8) * 132 + c], Wb[(2 * tig + 9) * 132 + c]);
        }
        #pragma unroll
        for (int mf = 0; mf < 4; mf++)
            #pragma unroll
            for (int nf = 0; nf < 8; nf++) {
                mmah(C[mf][nf], al[mf], bw[nf]);
                mmah(C[mf][nf], ah[mf], bw[nf]);
            }
    }

    unsigned* out = g_scr[which];
    if (which < 2) {
        // Q (pre-scaled) / K: [bh][s][32 words slot16]; one packed word per (mf,half,nf)
        const float sc = (which == 0) ? QSC : 1.0f;
        #pragma unroll
        for (int mf = 0; mf < 4; mf++) {
            int R = m0 + wm * 64 + mf * 16 + gid;
            #pragma unroll
            for (int half = 0; half < 2; half++) {
                int Rr = R + half * 8;
                int bb = Rr >> 11;
                int s  = Rr & 2047;
                #pragma unroll
                for (int nf = 0; nf < 8; nf++) {
                    int Cc = n0 + wn * 64 + nf * 8 + tig * 2;
                    int hh = Cc >> 6, dd = Cc & 63;
                    int wword = dd >> 1;     // dd is even
                    unsigned* base = out + ((size_t)(bb * NH + hh) * SS + s) * 32;
                    base[SLOT16(wword)] = packh2(C[mf][nf][half * 2 + 0] * sc,
                                                 C[mf][nf][half * 2 + 1] * sc);
                }
            }
        }
    } else {
        // V: [bh][d][SS/2 words], key order pi within 64-groups, slot16 positions.
        float (*stg)[129] = (float(*)[129])sbuf;
        #pragma unroll
        for (int ch = 0; ch < 2; ch++) {
            __syncthreads();
            if (wm == ch) {
                #pragma unroll
                for (int mf = 0; mf < 4; mf++)
                    #pragma unroll
                    for (int half = 0; half < 2; half++) {
                        int rr = mf * 16 + half * 8 + gid;
                        #pragma unroll
                        for (int nf = 0; nf < 8; nf++) {
                            int cc = wn * 64 + nf * 8 + tig * 2;
                            stg[rr][cc]     = C[mf][nf][half * 2 + 0];
                            stg[rr][cc + 1] = C[mf][nf][half * 2 + 1];
                        }
                    }
            }
            __syncthreads();
            const int base_s = m0 + ch * 64;
            const int bb = base_s >> 11;
            const int s_loc = base_s & 2047;
            const int grp = s_loc >> 6;
            #pragma unroll
            for (int cc = 0; cc < 32; cc++) {
                int c = w * 32 + cc;
                int hh = (n0 + c) >> 6, dd = (n0 + c) & 63;
                __half* drow = (__half*)(out + ((size_t)(bb * NH + hh) * HD + dd) * (SS / 2)
                                             + (size_t)grp * 32);
                #pragma unroll
                for (int sg = 0; sg < 2; sg++) {
                    int s = sg * 32 + lane;           // key within group
                    int mm = s & 7;
                    int x = (s & 0x38) | ((mm & 3) << 1) | (mm >> 2);  // pi^-1
                    int u = x >> 1, eps = x & 1;
                    drow[SLOT16(u) * 2 + eps] = __float2half_rn(stg[s][c]);
                }
            }
        }
    }
}

// ---------------------------------------------------------------------------
// Flash attention, fp16 m16n8k16 mma. 128-q tile, 4 warps x 32 rows.
// P in registers (packed fp16x2 pairs == PV A-frag via pi key ordering).
// K/V double-buffered via cp.async into pre-permuted fp16 layout.
// ---------------------------------------------------------------------------
__global__ __launch_bounds__(128, 2) void attn_kernel(
    const int* __restrict__ v_mask, const int* __restrict__ q_mask,
    float* __restrict__ out)
{
    extern __shared__ unsigned smu[];
    unsigned* Qp = smu;                  // [128][36] (32 words + pad)
    unsigned* KV = smu + 128 * 36;       // [2][ K:64*36 | V:64*36 ]
    float* kbb  = (float*)(KV + 4 * 64 * 36);   // [2][64]

    const int tid = threadIdx.x;
    const int lane = tid & 31;
    const int w = tid >> 5;
    const int gid = lane >> 2, tig = lane & 3;
    const int qt = gridDim.x - 1 - blockIdx.x;
    const int bh = blockIdx.y;
    const int b = bh >> 4, h = bh & 15;
    const int q0 = qt * 128;
    const int kt_hi = (q0 + 127) >> 6;
    const int NT = SS / 64;

    const unsigned* Qg = g_scr[0] + (size_t)bh * SS * 32;
    const unsigned* Kg = g_scr[1] + (size_t)bh * SS * 32;
    const unsigned* Vg = g_scr[2] + (size_t)bh * HD * (SS / 2);

    unsigned sb = (unsigned)__cvta_generic_to_shared(smu);
    const int llr = tid >> 1;            // row 0..63
    const int lh16 = (tid & 1) * 16;     // word offset 0/16
    unsigned kdst[2], vdst[2];
    #pragma unroll
    for (int s = 0; s < 2; s++) {
        unsigned base = sb + (128 * 36 + s * 2 * 64 * 36) * 4;
        kdst[s] = base + (llr * 36 + lh16) * 4;
        vdst[s] = base + (64 * 36 + llr * 36 + lh16) * 4;
    }

    // prologue: Q tile + K/V tile 0 + kb(0)
    {
        unsigned qdst = sb + (tid * 36) * 4;
        const unsigned* qsrc = Qg + (size_t)(q0 + tid) * 32;
        #pragma unroll
        for (int j = 0; j < 8; j++)
            cp16(qdst + j * 16, qsrc + j * 4);
        const unsigned* ksrc = Kg + (size_t)llr * 32 + lh16;
        const unsigned* vsrc = Vg + (size_t)llr * (SS / 2) + lh16;
        #pragma unroll
        for (int j = 0; j < 4; j++) {
            cp16(kdst[0] + j * 16, ksrc + j * 4);
            cp16(vdst[0] + j * 16, vsrc + j * 4);
        }
        if (tid < 64) kbb[tid] = v_mask[b * SS + tid] ? 0.f : -CMSK;
        CP_COMMIT();
    }

    const float NEG_INF = __int_as_float(0xff800000);
    float m[2][2] = {{NEG_INF, NEG_INF}, {NEG_INF, NEG_INF}};
    float l[2][2] = {{0.f, 0.f}, {0.f, 0.f}};
    float acc[2][8][4];
    #pragma unroll
    for (int mf = 0; mf < 2; mf++)
        #pragma unroll
        for (int of = 0; of < 8; of++)
            #pragma unroll
            for (int e = 0; e < 4; e++) acc[mf][of][e] = 0.f;

    int deg = 0;
    const int rq = w * 32 + gid;
    const int kap = (gid >> 1) + ((gid & 1) << 2);   // kappa(gid)
    const int qo0 = rq * 36 + tig * 8;
    const int qo1 = (rq + 8) * 36 + tig * 8;
    const int qo2 = (rq + 16) * 36 + tig * 8;
    const int qo3 = (rq + 24) * 36 + tig * 8;

    float rkb = 0.f;

    for (int kt = 0; kt < NT; kt++) {
        if (kt > kt_hi && !deg) { CP_WAIT0(); break; }
        const int k0 = kt * 64;
        const int cur = kt & 1, nxt = cur ^ 1;
        const unsigned* Kp = KV + cur * (2 * 64 * 36);
        const unsigned* Vp = Kp + 64 * 36;
        const float* kb = kbb + cur * 64;
        const bool pf = (kt + 1 < NT);

        CP_WAIT0();
        __syncthreads();

        // ---- QK (fp16): 2 uint4 per operand row cover all 4 k16 steps ----
        float sc[2][8][4];
        #pragma unroll
        for (int mf = 0; mf < 2; mf++)
            #pragma unroll
            for (int nf = 0; nf < 8; nf++)
                #pragma unroll
                for (int e = 0; e < 4; e++) sc[mf][nf][e] = 0.f;

        #pragma unroll
        for (int j = 0; j < 2; j++) {
            uint4 a0 = *(const uint4*)&Qp[qo0 + j * 4];
            uint4 a1 = *(const uint4*)&Qp[qo1 + j * 4];
            uint4 a2 = *(const uint4*)&Qp[qo2 + j * 4];
            uint4 a3 = *(const uint4*)&Qp[qo3 + j * 4];
            unsigned Ae0[4] = {a0.x, a1.x, a0.y, a1.y};
            unsigned Ao0[4] = {a0.z, a1.z, a0.w, a1.w};
            unsigned Ae1[4] = {a2.x, a3.x, a2.y, a3.y};
            unsigned Ao1[4] = {a2.z, a3.z, a2.w, a3.w};
            #pragma unroll
            for (int nf = 0; nf < 8; nf++) {
                uint4 bv = *(const uint4*)&Kp[(nf * 8 + kap) * 36 + tig * 8 + j * 4];
                unsigned Be[2] = {bv.x, bv.y};
                unsigned Bo[2] = {bv.z, bv.w};
                mmah(sc[0][nf], Ae0, Be);
                mmah(sc[0][nf], Ao0, Bo);
                mmah(sc[1][nf], Ae1, Be);
                mmah(sc[1][nf], Ao1, Bo);
            }
        }

        // ---- issue cp.async for tile kt+1 ----
        if (pf) {
            const int nk0 = k0 + 64;
            const unsigned* ksrc = Kg + (size_t)(nk0 + llr) * 32 + lh16;
            const unsigned* vsrc = Vg + (size_t)llr * (SS / 2) + (nk0 >> 1) + lh16;
            #pragma unroll
            for (int j = 0; j < 4; j++) {
                cp16(kdst[nxt] + j * 16, ksrc + j * 4);
                cp16(vdst[nxt] + j * 16, vsrc + j * 4);
            }
            CP_COMMIT();
            if (tid < 64) rkb = v_mask[b * SS + nk0 + tid] ? 0.f : -CMSK;
        }

        // ---- mask + online softmax; sc[mf][nf][2i+jj] <-> key nf*8+tig+4*jj ----
        float kb0[8], kb1[8];
        #pragma unroll
        for (int nf = 0; nf < 8; nf++) {
            kb0[nf] = kb[nf * 8 + tig];
            kb1[nf] = kb[nf * 8 + tig + 4];
        }
        #pragma unroll
        for (int mf = 0; mf < 2; mf++)
            #pragma unroll
            for (int i = 0; i < 2; i++) {
                int qg = q0 + rq + mf * 16 + 8 * i;
                float mx = NEG_INF;
                #pragma unroll
                for (int nf = 0; nf < 8; nf++) {
                    float s0 = sc[mf][nf][2 * i + 0] + kb0[nf];
                    float s1 = sc[mf][nf][2 * i + 1] + kb1[nf];
                    if (k0 + nf * 8 + tig > qg)     s0 -= CMSK;
                    if (k0 + nf * 8 + tig + 4 > qg) s1 -= CMSK;
                    sc[mf][nf][2 * i + 0] = s0;
                    sc[mf][nf][2 * i + 1] = s1;
                    mx = fmaxf(mx, fmaxf(s0, s1));
                }
                mx = fmaxf(mx, __shfl_xor_sync(0xffffffffu, mx, 1));
                mx = fmaxf(mx, __shfl_xor_sync(0xffffffffu, mx, 2));
                float nm = fmaxf(m[mf][i], mx);
                float rs = 0.f;
                #pragma unroll
                for (int nf = 0; nf < 8; nf++)
                    #pragma unroll
                    for (int jj = 0; jj < 2; jj++) {
                        float p = ex2(sc[mf][nf][2 * i + jj] - nm);
                        rs += p;
                        sc[mf][nf][2 * i + jj] = p;
                    }
                rs += __shfl_xor_sync(0xffffffffu, rs, 1);
                rs += __shfl_xor_sync(0xffffffffu, rs, 2);
                float alpha = ex2(m[mf][i] - nm);
                l[mf][i] = l[mf][i] * alpha + rs;
                m[mf][i] = nm;
                #pragma unroll
                for (int of = 0; of < 8; of++) {
                    acc[mf][of][2 * i + 0] *= alpha;
                    acc[mf][of][2 * i + 1] *= alpha;
                }
            }

        // ---- pack P into fp16 A-fragments (pi key order) ----
        unsigned Pw[2][4][4];
        #pragma unroll
        for (int mf = 0; mf < 2; mf++)
            #pragma unroll
            for (int kk = 0; kk < 4; kk++) {
                Pw[mf][kk][0] = packh2(sc[mf][2 * kk][0],     sc[mf][2 * kk][1]);
                Pw[mf][kk][1] = packh2(sc[mf][2 * kk][2],     sc[mf][2 * kk][3]);
                Pw[mf][kk][2] = packh2(sc[mf][2 * kk + 1][0], sc[mf][2 * kk + 1][1]);
                Pw[mf][kk][3] = packh2(sc[mf][2 * kk + 1][2], sc[mf][2 * kk + 1][3]);
            }

        // ---- PV (fp16): O += P @ V ----
        #pragma unroll
        for (int of = 0; of < 8; of++) {
            const unsigned* vb = &Vp[(of * 8 + gid) * 36 + tig * 8];
            uint4 v0 = *(const uint4*)(vb);
            uint4 v1 = *(const uint4*)(vb + 4);
            unsigned B0[2] = {v0.x, v0.y};
            unsigned B1[2] = {v0.z, v0.w};
            unsigned B2[2] = {v1.x, v1.y};
            unsigned B3[2] = {v1.z, v1.w};
            #pragma unroll
            for (int mf = 0; mf < 2; mf++) {
                mmah(acc[mf][of], Pw[mf][0], B0);
                mmah(acc[mf][of], Pw[mf][1], B1);
                mmah(acc[mf][of], Pw[mf][2], B2);
                mmah(acc[mf][of], Pw[mf][3], B3);
            }
        }

        if (pf && tid < 64) kbb[nxt * 64 + tid] = rkb;

        if (kt == kt_hi)
            deg = __syncthreads_or((m[0][0] < -1e10f) || (m[0][1] < -1e10f) ||
                                   (m[1][0] < -1e10f) || (m[1][1] < -1e10f));
    }

    // epilogue
    #pragma unroll
    for (int mf = 0; mf < 2; mf++)
        #pragma unroll
        for (int i = 0; i < 2; i++) {
            int qg = q0 + rq + mf * 16 + 8 * i;
            float qm = (float)q_mask[b * SS + qg];
            float f = qm / l[mf][i];
            #pragma unroll
            for (int of = 0; of < 8; of++) {
                float2 o = make_float2(acc[mf][of][2 * i + 0] * f, acc[mf][of][2 * i + 1] * f);
                *(float2*)(out + ((size_t)b * SS + qg) * ND + h * HD + of * 8 + tig * 2) = o;
            }
        }
}

// ---------------------------------------------------------------------------
extern "C" void kernel_launch(void* const* d_in, const int* in_sizes, int n_in,
                              void* d_out, int out_size)
{
    const float* q  = (const float*)d_in[0];
    const float* k  = (const float*)d_in[1];
    const float* v  = (const float*)d_in[2];
    const int* vmask = (const int*)d_in[3];
    const int* qmask = (const int*)d_in[4];
    const float* Wq = (const float*)d_in[5];
    const float* Wk = (const float*)d_in[6];
    const float* Wv = (const float*)d_in[7];
    float* out = (float*)d_out;

    const int smem_attn = (128 * 36 + 4 * 64 * 36 + 2 * 64) * 4;   // 55,808 B
    cudaFuncSetAttribute(attn_kernel, cudaFuncAttributeMaxDynamicSharedMemorySize, smem_attn);

    dim3 gp(ND / 128, (BB * SS) / 128, 3);   // (8, 32, 3)
    proj_kernel<<<gp, 128>>>(q, k, v, Wq, Wk, Wv);

    dim3 ga(SS / 128, BB * NH);              // (16, 32)
    attn_kernel<<<ga, 128, smem_attn>>>(vmask, qmask, out);
}